// round 8
// baseline (speedup 1.0000x reference)
#include <cuda_runtime.h>

#define TPB    96         // threads per block; each owns 8 floats (half a row)
#define NCOLS  192        // thread-columns per full row (1536/8)
#define BAND   16         // output rows per block
#define HH     384
#define ROWF   1536       // W*C floats per row
#define NBANDS (HH / BAND)

static __device__ __forceinline__ int hrefl(int h) {
    // reflect-101 along height; used only for h in [-2, HH+1]
    h = (h < 0) ? -h : h;
    return (h >= HH) ? (2 * HH - 2 - h) : h;
}

// Gaussian taps for ksize=5, sigma=1.1 (OpenCV default), normalized.
#define C0 0.07076630f    /* w[0] = w[4] */
#define C1 0.24446028f    /* w[1] = w[3] */
#define C2 0.36954642f    /* w[2]        */

struct F8 { float v[8]; };

// Load row h and horizontally blur this thread's 8 floats (flats 8g..8g+7).
// Intra-warp halo via shuffles; warp-edge lanes load their 6-float halo;
// image width edges fold reflect-101 into a register permutation.
static __device__ __forceinline__ F8 hb_row(
    const float* __restrict__ ib, int h, int g, int lane)
{
    const float* __restrict__ rp = ib + (long)hrefl(h) * ROWF + 8 * g;
    float4 Cb = *(const float4*)(rp);       // flats 8g   .. 8g+3
    float4 Db = *(const float4*)(rp + 4);   // flats 8g+4 .. 8g+7

    // e[k] = flat(8g - 6 + k), k = 0..19
    float e0  = __shfl_up_sync(0xffffffffu, Cb.z, 1);
    float e1  = __shfl_up_sync(0xffffffffu, Cb.w, 1);
    float e2  = __shfl_up_sync(0xffffffffu, Db.x, 1);
    float e3  = __shfl_up_sync(0xffffffffu, Db.y, 1);
    float e4  = __shfl_up_sync(0xffffffffu, Db.z, 1);
    float e5  = __shfl_up_sync(0xffffffffu, Db.w, 1);
    float e14 = __shfl_down_sync(0xffffffffu, Cb.x, 1);
    float e15 = __shfl_down_sync(0xffffffffu, Cb.y, 1);
    float e16 = __shfl_down_sync(0xffffffffu, Cb.z, 1);
    float e17 = __shfl_down_sync(0xffffffffu, Cb.w, 1);
    float e18 = __shfl_down_sync(0xffffffffu, Db.x, 1);
    float e19 = __shfl_down_sync(0xffffffffu, Db.y, 1);

    // Cross-warp halo (lanes 0/31): direct loads.
    if (lane == 0 && g > 0) {
        float2 a = *(const float2*)(rp - 6);
        float4 b = *(const float4*)(rp - 4);
        e0 = a.x; e1 = a.y; e2 = b.x; e3 = b.y; e4 = b.z; e5 = b.w;
    }
    if (lane == 31 && g < NCOLS - 1) {
        float4 b = *(const float4*)(rp + 8);
        float2 a = *(const float2*)(rp + 12);
        e14 = b.x; e15 = b.y; e16 = b.z; e17 = b.w; e18 = a.x; e19 = a.y;
    }
    // Image width edges.
    if (g == 0) {            // flats -6..-1 -> reflected {6,7,8,3,4,5}
        e0 = Db.z; e1 = Db.w; e2 = e14; e3 = Cb.w; e4 = Db.x; e5 = Db.y;
    }
    if (g == NCOLS - 1) {    // flats 1536..1541 -> {1530,1531,1532,1527,1528,1529}
        e14 = Cb.z; e15 = Cb.w; e16 = Db.x; e17 = e5; e18 = Cb.x; e19 = Cb.y;
    }

    const float e6 = Cb.x, e7 = Cb.y, e8 = Cb.z, e9 = Cb.w;
    const float e10 = Db.x, e11 = Db.y, e12 = Db.z, e13 = Db.w;

    // Horizontal taps at flat offsets {-6,-3,0,+3,+6}.
    F8 o;
    o.v[0] = C0 * (e0 + e12) + C1 * (e3  + e9)  + C2 * e6;
    o.v[1] = C0 * (e1 + e13) + C1 * (e4  + e10) + C2 * e7;
    o.v[2] = C0 * (e2 + e14) + C1 * (e5  + e11) + C2 * e8;
    o.v[3] = C0 * (e3 + e15) + C1 * (e6  + e12) + C2 * e9;
    o.v[4] = C0 * (e4 + e16) + C1 * (e7  + e13) + C2 * e10;
    o.v[5] = C0 * (e5 + e17) + C1 * (e8  + e14) + C2 * e11;
    o.v[6] = C0 * (e6 + e18) + C1 * (e9  + e15) + C2 * e12;
    o.v[7] = C0 * (e7 + e19) + C1 * (e10 + e16) + C2 * e13;
    return o;
}

__global__ void __launch_bounds__(TPB, 10)
gauss5_kernel(const float* __restrict__ x, float* __restrict__ y)
{
    const int t    = threadIdx.x;
    const int lane = t & 31;
    const int g    = blockIdx.x * TPB + t;   // global thread-column, 0..191
    const int h0   = blockIdx.y * BAND;
    const long img = blockIdx.z;

    const float* __restrict__ ib = x + img * (long)(HH * ROWF);
    float*       __restrict__ ob = y + img * (long)(HH * ROWF) + 8 * g;

    // Rolling vertical partial sums over hb rows. After processing hb row w_k:
    //   T0 -> out_{k-1} (awaits c0*w_{k+1}),  T1 -> out_k,  T2 -> out_{k+1},
    //   T3 -> out_{k+2}.
    F8 T0, T1, T2, T3;

    // Prologue: rows h0-2 .. h0+1 feed the accumulators, nothing emitted.
    {
        F8 w = hb_row(ib, h0 - 2, g, lane);
        #pragma unroll
        for (int j = 0; j < 8; j++) {
            T3.v[j] = C0 * w.v[j]; T2.v[j] = C1 * w.v[j];
            T1.v[j] = C2 * w.v[j]; T0.v[j] = C1 * w.v[j];
        }
        w = hb_row(ib, h0 - 1, g, lane);
        #pragma unroll
        for (int j = 0; j < 8; j++) {
            T0.v[j] = T1.v[j] + C1 * w.v[j];
            T1.v[j] = T2.v[j] + C2 * w.v[j];
            T2.v[j] = T3.v[j] + C1 * w.v[j];
            T3.v[j] = C0 * w.v[j];
        }
        w = hb_row(ib, h0, g, lane);
        #pragma unroll
        for (int j = 0; j < 8; j++) {
            T0.v[j] = T1.v[j] + C1 * w.v[j];
            T1.v[j] = T2.v[j] + C2 * w.v[j];
            T2.v[j] = T3.v[j] + C1 * w.v[j];
            T3.v[j] = C0 * w.v[j];
        }
        w = hb_row(ib, h0 + 1, g, lane);
        #pragma unroll
        for (int j = 0; j < 8; j++) {
            T0.v[j] = T1.v[j] + C1 * w.v[j];
            T1.v[j] = T2.v[j] + C2 * w.v[j];
            T2.v[j] = T3.v[j] + C1 * w.v[j];
            T3.v[j] = C0 * w.v[j];
        }
    }

    // Main loop: processing hb row h0+2+r emits output row h0+r.
    #pragma unroll 4
    for (int r = 0; r < BAND; r++) {
        F8 w = hb_row(ib, h0 + 2 + r, g, lane);

        float4 oa, obv;
        oa.x  = T0.v[0] + C0 * w.v[0];
        oa.y  = T0.v[1] + C0 * w.v[1];
        oa.z  = T0.v[2] + C0 * w.v[2];
        oa.w  = T0.v[3] + C0 * w.v[3];
        obv.x = T0.v[4] + C0 * w.v[4];
        obv.y = T0.v[5] + C0 * w.v[5];
        obv.z = T0.v[6] + C0 * w.v[6];
        obv.w = T0.v[7] + C0 * w.v[7];

        float* op = ob + (long)(h0 + r) * ROWF;
        *(float4*)op       = oa;
        *(float4*)(op + 4) = obv;

        #pragma unroll
        for (int j = 0; j < 8; j++) {
            T0.v[j] = T1.v[j] + C1 * w.v[j];
            T1.v[j] = T2.v[j] + C2 * w.v[j];
            T2.v[j] = T3.v[j] + C1 * w.v[j];
            T3.v[j] = C0 * w.v[j];
        }
    }
}

extern "C" void kernel_launch(void* const* d_in, const int* in_sizes, int n_in,
                              void* d_out, int out_size)
{
    const float* x = (const float*)d_in[0];
    float* y = (float*)d_out;
    const int batch = in_sizes[0] / (HH * ROWF);   // 64
    dim3 grid(NCOLS / TPB, NBANDS, batch);
    gauss5_kernel<<<grid, TPB>>>(x, y);
}

// round 9
// speedup vs baseline: 1.4087x; 1.4087x over previous
#include <cuda_runtime.h>
#include <cstdint>

#define TPB    192        // one thread per 8 floats of a 1536-float row
#define NCOLS  192
#define BAND   16         // output rows per block
#define NROWS  (BAND + 4) // input rows consumed per band = 20
#define NSLOT  7          // smem ring slots (6 KB each)
#define HH     384
#define ROWF   1536
#define ROWB   (ROWF * 4) // 6144 bytes per row
#define NBANDS (HH / BAND)

static __device__ __forceinline__ int hrefl(int h) {
    h = (h < 0) ? -h : h;
    return (h >= HH) ? (2 * HH - 2 - h) : h;
}

// Gaussian taps for ksize=5, sigma=1.1 (OpenCV default), normalized.
#define C0 0.07076630f
#define C1 0.24446028f
#define C2 0.36954642f

struct F8 { float v[8]; };

static __device__ __forceinline__ uint32_t s2u(const void* p) {
    uint32_t a;
    asm("{ .reg .u64 t; cvta.to.shared.u64 t, %1; cvt.u32.u64 %0, t; }"
        : "=r"(a) : "l"(p));
    return a;
}

static __device__ __forceinline__ void mbar_init(uint32_t mbar, uint32_t cnt) {
    asm volatile("mbarrier.init.shared.b64 [%0], %1;" :: "r"(mbar), "r"(cnt) : "memory");
}
static __device__ __forceinline__ void mbar_expect_tx(uint32_t mbar, uint32_t bytes) {
    asm volatile("mbarrier.arrive.expect_tx.shared.b64 _, [%0], %1;"
                 :: "r"(mbar), "r"(bytes) : "memory");
}
static __device__ __forceinline__ void bulk_ldg(uint32_t dst, const void* src, uint32_t mbar) {
    asm volatile("cp.async.bulk.shared::cluster.global.mbarrier::complete_tx::bytes "
                 "[%0], [%1], %2, [%3];"
                 :: "r"(dst), "l"(src), "r"((uint32_t)ROWB), "r"(mbar) : "memory");
}
static __device__ __forceinline__ void mbar_wait(uint32_t mbar, uint32_t parity) {
    asm volatile(
        "{\n\t"
        ".reg .pred P;\n\t"
        "LAB_%=:\n\t"
        "mbarrier.try_wait.parity.acquire.cta.shared::cta.b64 P, [%0], %1, 0x989680;\n\t"
        "@P bra.uni DONE_%=;\n\t"
        "bra.uni LAB_%=;\n\t"
        "DONE_%=:\n\t"
        "}" :: "r"(mbar), "r"(parity) : "memory");
}

// Horizontal blur of this thread's 8 floats (flats 8g..8g+7) of the row held
// in smem slot `srow`. Halo comes straight from smem; image width edges fold
// reflect-101 into a register permutation of already-loaded values.
static __device__ __forceinline__ F8 hb_row(const float* __restrict__ srow, int g)
{
    const float* s = srow + 8 * g;
    float4 Cb = *(const float4*)(s);       // e6..e9
    float4 Db = *(const float4*)(s + 4);   // e10..e13
    float e0 = 0.f, e1 = 0.f, e2 = 0.f, e3 = 0.f, e4 = 0.f, e5 = 0.f;
    float e14 = 0.f, e15 = 0.f, e16 = 0.f, e17 = 0.f, e18 = 0.f, e19 = 0.f;

    if (g > 0) {                       // flats 8g-6 .. 8g-1
        float2 a = *(const float2*)(s - 6);
        float4 b = *(const float4*)(s - 4);
        e0 = a.x; e1 = a.y; e2 = b.x; e3 = b.y; e4 = b.z; e5 = b.w;
    }
    if (g < NCOLS - 1) {               // flats 8g+8 .. 8g+13
        float4 b = *(const float4*)(s + 8);
        float2 a = *(const float2*)(s + 12);
        e14 = b.x; e15 = b.y; e16 = b.z; e17 = b.w; e18 = a.x; e19 = a.y;
    }
    if (g == 0) {            // flats -6..-1 -> reflected {6,7,8,3,4,5}
        e0 = Db.z; e1 = Db.w; e2 = e14; e3 = Cb.w; e4 = Db.x; e5 = Db.y;
    }
    if (g == NCOLS - 1) {    // flats 1536..1541 -> {1530,1531,1532,1527,1528,1529}
        e14 = Cb.z; e15 = Cb.w; e16 = Db.x; e17 = e5; e18 = Cb.x; e19 = Cb.y;
    }

    const float e6 = Cb.x, e7 = Cb.y, e8 = Cb.z, e9 = Cb.w;
    const float e10 = Db.x, e11 = Db.y, e12 = Db.z, e13 = Db.w;

    F8 o;
    o.v[0] = C0 * (e0 + e12) + C1 * (e3  + e9)  + C2 * e6;
    o.v[1] = C0 * (e1 + e13) + C1 * (e4  + e10) + C2 * e7;
    o.v[2] = C0 * (e2 + e14) + C1 * (e5  + e11) + C2 * e8;
    o.v[3] = C0 * (e3 + e15) + C1 * (e6  + e12) + C2 * e9;
    o.v[4] = C0 * (e4 + e16) + C1 * (e7  + e13) + C2 * e10;
    o.v[5] = C0 * (e5 + e17) + C1 * (e8  + e14) + C2 * e11;
    o.v[6] = C0 * (e6 + e18) + C1 * (e9  + e15) + C2 * e12;
    o.v[7] = C0 * (e7 + e19) + C1 * (e10 + e16) + C2 * e13;
    return o;
}

__global__ void __launch_bounds__(TPB, 4)
gauss5_kernel(const float* __restrict__ x, float* __restrict__ y)
{
    __shared__ float ring[NSLOT][ROWF];                 // 42 KB
    __shared__ __align__(8) unsigned long long mbar[NSLOT];

    const int t   = threadIdx.x;                        // == g (thread-column)
    const int h0  = blockIdx.x * BAND;
    const long img = blockIdx.y;

    const float* __restrict__ ib = x + img * (long)(HH * ROWF);
    float*       __restrict__ ob = y + img * (long)(HH * ROWF) + 8 * t;

    uint32_t mb[NSLOT];
    #pragma unroll
    for (int s = 0; s < NSLOT; s++) mb[s] = s2u(&mbar[s]);

    if (t == 0) {
        #pragma unroll
        for (int s = 0; s < NSLOT; s++) mbar_init(mb[s], 1);
    }
    __syncthreads();

    // Prologue: fill the ring with input rows k = 0..6 (row h0-2+k).
    if (t == 0) {
        #pragma unroll
        for (int k = 0; k < NSLOT; k++) {
            mbar_expect_tx(mb[k], ROWB);
            bulk_ldg(s2u(ring[k]), ib + (long)hrefl(h0 - 2 + k) * ROWF, mb[k]);
        }
    }

    // Rows k = 0..3: fill the vertical window, emit nothing.
    F8 w0, w1, w2, w3;
    #pragma unroll
    for (int k = 0; k < 4; k++) {
        mbar_wait(mb[k], 0);
        F8 w = hb_row(ring[k], t);
        if (k == 0) w0 = w; else if (k == 1) w1 = w;
        else if (k == 2) w2 = w; else w3 = w;
        __syncthreads();                      // all threads done with slot k
        if (t == 0) {                         // refill it with row k+7
            mbar_expect_tx(mb[k], ROWB);
            bulk_ldg(s2u(ring[k]), ib + (long)hrefl(h0 - 2 + k + NSLOT) * ROWF, mb[k]);
        }
    }

    // Main: consuming input row k emits output row h0 + k - 4.
    #pragma unroll 4
    for (int k = 4; k < NROWS; k++) {
        const int slot = k % NSLOT;
        mbar_wait(mb[slot], (k / NSLOT) & 1);
        F8 w4 = hb_row(ring[slot], t);

        float4 oa, obv;
        oa.x  = C0 * (w0.v[0] + w4.v[0]) + C1 * (w1.v[0] + w3.v[0]) + C2 * w2.v[0];
        oa.y  = C0 * (w0.v[1] + w4.v[1]) + C1 * (w1.v[1] + w3.v[1]) + C2 * w2.v[1];
        oa.z  = C0 * (w0.v[2] + w4.v[2]) + C1 * (w1.v[2] + w3.v[2]) + C2 * w2.v[2];
        oa.w  = C0 * (w0.v[3] + w4.v[3]) + C1 * (w1.v[3] + w3.v[3]) + C2 * w2.v[3];
        obv.x = C0 * (w0.v[4] + w4.v[4]) + C1 * (w1.v[4] + w3.v[4]) + C2 * w2.v[4];
        obv.y = C0 * (w0.v[5] + w4.v[5]) + C1 * (w1.v[5] + w3.v[5]) + C2 * w2.v[5];
        obv.z = C0 * (w0.v[6] + w4.v[6]) + C1 * (w1.v[6] + w3.v[6]) + C2 * w2.v[6];
        obv.w = C0 * (w0.v[7] + w4.v[7]) + C1 * (w1.v[7] + w3.v[7]) + C2 * w2.v[7];

        float* op = ob + (long)(h0 + k - 4) * ROWF;
        *(float4*)op       = oa;
        *(float4*)(op + 4) = obv;

        w0 = w1; w1 = w2; w2 = w3; w3 = w4;

        __syncthreads();                      // all threads done with this slot
        if (t == 0 && k + NSLOT < NROWS) {    // refill with row k+7
            mbar_expect_tx(mb[slot], ROWB);
            bulk_ldg(s2u(ring[slot]), ib + (long)hrefl(h0 - 2 + k + NSLOT) * ROWF, mb[slot]);
        }
    }
}

extern "C" void kernel_launch(void* const* d_in, const int* in_sizes, int n_in,
                              void* d_out, int out_size)
{
    const float* x = (const float*)d_in[0];
    float* y = (float*)d_out;
    const int batch = in_sizes[0] / (HH * ROWF);   // 64
    dim3 grid(NBANDS, batch);
    gauss5_kernel<<<grid, TPB>>>(x, y);
}